// round 6
// baseline (speedup 1.0000x reference)
#include <cuda_runtime.h>
#include <math.h>

#define BB 16
#define CC 256
#define HH 128
#define WW 128
#define HWp (HH*WW)          // 16384
#define HW4 (HWp/4)          // 4096

// Scratch (device globals — no allocations allowed)
__device__ __align__(16) float g_sf[BB*2*HWp];     // [B,2,H,W]  avg(ch0), max(ch1)
__device__ __align__(16) float g_h1[BB*HWp*16];    // pixel-major [B,HW,16]
__device__ __align__(16) float g_samp[BB*2*HWp];   // [B,2,H,W]
__device__ __align__(16) float g_w2eff[2*9*16];    // transposed [d][wo][ic]
__device__ float g_b2eff[2];

// ---------------------------------------------------------------------------
// Kernel 1: channel reduce (avg + max over C=256). HBM-bound: 268 MB read.
// (R4 known-good configuration.)
// ---------------------------------------------------------------------------
__global__ void k_reduce(const float* __restrict__ x) {
    int idx = blockIdx.x * blockDim.x + threadIdx.x;   // 0..65535
    int b  = idx >> 12;
    int p4 = idx & 4095;
    const float4* xp = reinterpret_cast<const float4*>(x) + (size_t)b * CC * HW4 + p4;

    float4 s = make_float4(0.f, 0.f, 0.f, 0.f);
    float4 m = make_float4(-1e30f, -1e30f, -1e30f, -1e30f);
    #pragma unroll 8
    for (int c = 0; c < CC; ++c) {
        float4 v = __ldg(xp + (size_t)c * HW4);
        s.x += v.x; s.y += v.y; s.z += v.z; s.w += v.w;
        m.x = fmaxf(m.x, v.x); m.y = fmaxf(m.y, v.y);
        m.z = fmaxf(m.z, v.z); m.w = fmaxf(m.w, v.w);
    }
    const float inv = 1.0f / (float)CC;
    s.x *= inv; s.y *= inv; s.z *= inv; s.w *= inv;

    float4* o = reinterpret_cast<float4*>(g_sf);
    o[(size_t)b * 2 * HW4 + p4]       = s;   // avg  -> channel 0
    o[(size_t)b * 2 * HW4 + HW4 + p4] = m;   // max  -> channel 1
}

// ---------------------------------------------------------------------------
// Kernel 2: average w2/b2 over 49-channel groups (conv linear => exact),
// stored TRANSPOSED as [d][wo][ic].
// ---------------------------------------------------------------------------
__global__ void k_w2eff(const float* __restrict__ w2, const float* __restrict__ b2) {
    int i = threadIdx.x;
    if (i < 288) {
        int d  = i / 144;
        int r  = i % 144;
        int wo = r / 16;
        int ic = r % 16;
        float s = 0.f;
        #pragma unroll 7
        for (int j = 0; j < 49; ++j)
            s += w2[(size_t)(d * 49 + j) * 144 + ic * 9 + wo];
        g_w2eff[i] = s * (1.0f / 49.0f);
    }
    if (i < 2) {
        float s = 0.f;
        #pragma unroll 7
        for (int j = 0; j < 49; ++j) s += b2[i * 49 + j];
        g_b2eff[i] = s * (1.0f / 49.0f);
    }
}

// ---------------------------------------------------------------------------
// Kernel 3: conv3x3 (2->16) + BN + ReLU, smem-tiled, thread-quad channel
// split. Block = one 64-pixel row segment. Writes pixel-major h1.
// ---------------------------------------------------------------------------
__global__ void k_conv1(const float* __restrict__ w1,
                        const float* __restrict__ gamma, const float* __restrict__ beta,
                        const float* __restrict__ mean,  const float* __restrict__ var) {
    __shared__ float sf_s[2][3][68];   // 2 ch, 3 rows, 66 cols (+pad)
    __shared__ float ws[288];
    __shared__ float sc[16], bi[16];

    int t  = threadIdx.x;
    int bx = blockIdx.x;                 // b*256 + y*2 + xh
    int b  = bx >> 8;
    int y  = (bx >> 1) & 127;
    int x0 = (bx & 1) * 64;

    for (int i = t; i < 288; i += 256) ws[i] = w1[i];
    if (t < 16) {
        float s = gamma[t] * rsqrtf(var[t] + 1e-5f);
        sc[t] = s;
        bi[t] = beta[t] - mean[t] * s;
    }

    const float* sfb = g_sf + (size_t)b * 2 * HWp;
    for (int i = t; i < 396; i += 256) {
        int c   = i / 198;
        int rr  = (i % 198) / 66;
        int col = i % 66;
        int gy = y - 1 + rr, gx = x0 - 1 + col;
        float v = 0.f;
        if (gy >= 0 && gy < HH && gx >= 0 && gx < WW)
            v = sfb[c * HWp + gy * WW + gx];
        sf_s[c][rr][col] = v;
    }
    __syncthreads();

    int px = t >> 2;          // 0..63
    int q  = t & 3;           // channel quad: oc = 4q..4q+3

    float v[18];
    #pragma unroll
    for (int c = 0; c < 2; ++c)
        #pragma unroll
        for (int r = 0; r < 3; ++r)
            #pragma unroll
            for (int kw = 0; kw < 3; ++kw)
                v[c * 9 + r * 3 + kw] = sf_s[c][r][px + kw];

    float o[4];
    #pragma unroll
    for (int k4 = 0; k4 < 4; ++k4) {
        int oc = q * 4 + k4;
        float acc = 0.f;
        #pragma unroll
        for (int k = 0; k < 18; ++k) acc = fmaf(v[k], ws[oc * 18 + k], acc);
        o[k4] = fmaxf(fmaf(acc, sc[oc], bi[oc]), 0.f);
    }

    float4* hb = reinterpret_cast<float4*>(g_h1);
    hb[((size_t)b * HWp + y * WW + x0 + px) * 4 + q] = make_float4(o[0], o[1], o[2], o[3]);
}

// ---------------------------------------------------------------------------
// Kernel 4: conv3x3 (16->2 eff) + bias, tanh*0.5, grid, bilinear sample.
// Thread-quad channel split + shfl combine. 4 threads per pixel.
// ---------------------------------------------------------------------------
__global__ void k_off_sample() {
    __shared__ float4 ws[72];      // [d][wo][quad] of float4  (= [2][9][16] floats)
    __shared__ float b2s[2];
    int t = threadIdx.x;
    if (t < 72) ws[t] = reinterpret_cast<const float4*>(g_w2eff)[t];
    if (t < 2)  b2s[t] = g_b2eff[t];
    __syncthreads();

    int idx   = blockIdx.x * blockDim.x + t;   // 0..1048575
    int q     = idx & 3;
    int pixel = idx >> 2;                      // 0..262143
    int b     = pixel >> 14;
    int rem   = pixel & 16383;
    int y = rem >> 7, x = rem & 127;

    const float4* hb = reinterpret_cast<const float4*>(g_h1) + (size_t)b * HWp * 4 + q;
    float ax = 0.f, ay = 0.f;

    #pragma unroll
    for (int dy = 0; dy < 3; ++dy) {
        int yy = y + dy - 1;
        if (yy < 0 || yy >= HH) continue;
        #pragma unroll
        for (int dx = 0; dx < 3; ++dx) {
            int xx = x + dx - 1;
            if (xx < 0 || xx >= WW) continue;
            float4 h = hb[(size_t)(yy * WW + xx) * 4];
            int wo = dy * 3 + dx;
            float4 wxv = ws[wo * 4 + q];
            float4 wyv = ws[36 + wo * 4 + q];
            ax = fmaf(h.x, wxv.x, ax); ax = fmaf(h.y, wxv.y, ax);
            ax = fmaf(h.z, wxv.z, ax); ax = fmaf(h.w, wxv.w, ax);
            ay = fmaf(h.x, wyv.x, ay); ay = fmaf(h.y, wyv.y, ay);
            ay = fmaf(h.z, wyv.z, ay); ay = fmaf(h.w, wyv.w, ay);
        }
    }

    // combine the 4 channel-quads (lanes q=0..3 within each aligned quad)
    ax += __shfl_xor_sync(0xffffffffu, ax, 1);
    ax += __shfl_xor_sync(0xffffffffu, ax, 2);
    ay += __shfl_xor_sync(0xffffffffu, ay, 1);
    ay += __shfl_xor_sync(0xffffffffu, ay, 2);

    if (q == 0) {
        ax += b2s[0];
        ay += b2s[1];
        float txo = tanhf(ax) * 0.5f;
        float tyo = tanhf(ay) * 0.5f;
        float gxv = fmaf((float)x, 2.0f / 127.0f, -1.0f) + txo;
        float gyv = fmaf((float)y, 2.0f / 127.0f, -1.0f) + tyo;
        gxv = fminf(fmaxf(gxv, -1.f), 1.f);
        gyv = fminf(fmaxf(gyv, -1.f), 1.f);

        float ixf = ((gxv + 1.0f) * (float)WW - 1.0f) * 0.5f;
        float iyf = ((gyv + 1.0f) * (float)HH - 1.0f) * 0.5f;
        float x0f = floorf(ixf), y0f = floorf(iyf);
        int x0 = (int)x0f, y0 = (int)y0f;
        int x1 = x0 + 1,   y1 = y0 + 1;
        float wx1 = ixf - x0f, wx0 = 1.0f - wx1;
        float wy1 = iyf - y0f, wy0 = 1.0f - wy1;

        const float* s0 = g_sf + (size_t)b * 2 * HWp;  // avg
        const float* s1 = s0 + HWp;                    // max

        float w00 = wx0 * wy0, w10 = wx1 * wy0, w01 = wx0 * wy1, w11 = wx1 * wy1;
        bool vx0 = (x0 >= 0) & (x0 < WW), vx1 = (x1 >= 0) & (x1 < WW);
        bool vy0 = (y0 >= 0) & (y0 < HH), vy1 = (y1 >= 0) & (y1 < HH);

        float o0 = 0.f, o1 = 0.f;
        if (vy0 & vx0) { int p = y0 * WW + x0; o0 = fmaf(s0[p], w00, o0); o1 = fmaf(s1[p], w00, o1); }
        if (vy0 & vx1) { int p = y0 * WW + x1; o0 = fmaf(s0[p], w10, o0); o1 = fmaf(s1[p], w10, o1); }
        if (vy1 & vx0) { int p = y1 * WW + x0; o0 = fmaf(s0[p], w01, o0); o1 = fmaf(s1[p], w01, o1); }
        if (vy1 & vx1) { int p = y1 * WW + x1; o0 = fmaf(s0[p], w11, o0); o1 = fmaf(s1[p], w11, o1); }

        g_samp[(size_t)b * 2 * HWp + rem]       = o0;
        g_samp[(size_t)b * 2 * HWp + HWp + rem] = o1;
    }
}

// ---------------------------------------------------------------------------
// Kernel 5: conv7x7 (2->1, pad 3) + sigmoid. 4 px/thread (aligned float4).
// ---------------------------------------------------------------------------
__global__ void k_attn(const float* __restrict__ aw, float* __restrict__ out) {
    __shared__ float ws[98];
    int t = threadIdx.x;
    if (t < 98) ws[t] = aw[t];
    __syncthreads();

    int idx = blockIdx.x * blockDim.x + t;      // 0..65535
    int b   = idx >> 12;
    int p4  = idx & 4095;
    int y   = p4 >> 5;
    int x4  = (p4 & 31) * 4;

    const float* sb = g_samp + (size_t)b * 2 * HWp;
    float acc[4] = {0.f, 0.f, 0.f, 0.f};

    #pragma unroll
    for (int ch = 0; ch < 2; ++ch)
        #pragma unroll
        for (int dy = 0; dy < 7; ++dy) {
            int yy = y + dy - 3;
            if (yy < 0 || yy >= HH) continue;
            const float* base = sb + ch * HWp + yy * WW + x4;
            float4 mv = *reinterpret_cast<const float4*>(base);
            float cl[10];
            if (x4 > 0) {
                float4 lv = *reinterpret_cast<const float4*>(base - 4);
                cl[0] = lv.y; cl[1] = lv.z; cl[2] = lv.w;
            } else {
                cl[0] = cl[1] = cl[2] = 0.f;
            }
            cl[3] = mv.x; cl[4] = mv.y; cl[5] = mv.z; cl[6] = mv.w;
            if (x4 < 124) {
                float4 rv = *reinterpret_cast<const float4*>(base + 4);
                cl[7] = rv.x; cl[8] = rv.y; cl[9] = rv.z;
            } else {
                cl[7] = cl[8] = cl[9] = 0.f;
            }
            #pragma unroll
            for (int kw = 0; kw < 7; ++kw) {
                float w = ws[ch * 49 + dy * 7 + kw];
                #pragma unroll
                for (int j = 0; j < 4; ++j)
                    acc[j] = fmaf(cl[kw + j], w, acc[j]);
            }
        }

    float4 o;
    o.x = 1.0f / (1.0f + expf(-acc[0]));
    o.y = 1.0f / (1.0f + expf(-acc[1]));
    o.z = 1.0f / (1.0f + expf(-acc[2]));
    o.w = 1.0f / (1.0f + expf(-acc[3]));
    *reinterpret_cast<float4*>(out + (size_t)b * HWp + y * WW + x4) = o;
}

// ---------------------------------------------------------------------------
extern "C" void kernel_launch(void* const* d_in, const int* in_sizes, int n_in,
                              void* d_out, int out_size) {
    const float* x     = (const float*)d_in[0];
    const float* w1    = (const float*)d_in[1];
    const float* gamma = (const float*)d_in[2];
    const float* beta  = (const float*)d_in[3];
    const float* mean  = (const float*)d_in[4];
    const float* var   = (const float*)d_in[5];
    const float* w2    = (const float*)d_in[6];
    const float* b2    = (const float*)d_in[7];
    const float* aw    = (const float*)d_in[8];
    float* out = (float*)d_out;

    k_reduce<<<256, 256>>>(x);
    k_w2eff<<<1, 512>>>(w2, b2);
    k_conv1<<<4096, 256>>>(w1, gamma, beta, mean, var);
    k_off_sample<<<4096, 256>>>();
    k_attn<<<256, 256>>>(aw, out);
}

// round 7
// speedup vs baseline: 1.1568x; 1.1568x over previous
#include <cuda_runtime.h>
#include <cuda_fp16.h>
#include <math.h>

#define BB 16
#define CC 256
#define HH 128
#define WW 128
#define HWp (HH*WW)          // 16384
#define HW4 (HWp/4)          // 4096

// Scratch (device globals — no allocations allowed)
__device__ __align__(16) float  g_sf[BB*2*HWp];     // [B,2,H,W]  avg(ch0), max(ch1)
__device__ __align__(16) __half g_h1h[BB*HWp*16];   // pixel-major fp16 [B,HW,16] (8 MB)
__device__ __align__(16) float  g_samp[BB*2*HWp];   // [B,2,H,W]
__device__ __align__(16) float  g_w2eff[2*9*16];    // transposed [d][wo][ic]
__device__ float g_b2eff[2];

// ---------------------------------------------------------------------------
// Kernel 1: channel reduce (avg + max over C=256). HBM-bound: 268 MB read.
// <<<128,512>>>: exactly one block per SM (128 <= 148), perfectly balanced,
// 16 warps x MLP~8 per SM keeps DRAM saturated for the whole kernel.
// ---------------------------------------------------------------------------
__global__ void k_reduce(const float* __restrict__ x) {
    int idx = blockIdx.x * blockDim.x + threadIdx.x;   // 0..65535
    int b  = idx >> 12;
    int p4 = idx & 4095;
    const float4* xp = reinterpret_cast<const float4*>(x) + (size_t)b * CC * HW4 + p4;

    float4 s = make_float4(0.f, 0.f, 0.f, 0.f);
    float4 m = make_float4(-1e30f, -1e30f, -1e30f, -1e30f);
    #pragma unroll 8
    for (int c = 0; c < CC; ++c) {
        float4 v = __ldg(xp + (size_t)c * HW4);
        s.x += v.x; s.y += v.y; s.z += v.z; s.w += v.w;
        m.x = fmaxf(m.x, v.x); m.y = fmaxf(m.y, v.y);
        m.z = fmaxf(m.z, v.z); m.w = fmaxf(m.w, v.w);
    }
    const float inv = 1.0f / (float)CC;
    s.x *= inv; s.y *= inv; s.z *= inv; s.w *= inv;

    float4* o = reinterpret_cast<float4*>(g_sf);
    o[(size_t)b * 2 * HW4 + p4]       = s;   // avg  -> channel 0
    o[(size_t)b * 2 * HW4 + HW4 + p4] = m;   // max  -> channel 1
}

// ---------------------------------------------------------------------------
// Kernel 2: average w2/b2 over 49-channel groups (conv linear => exact),
// stored TRANSPOSED as [d][wo][ic].
// ---------------------------------------------------------------------------
__global__ void k_w2eff(const float* __restrict__ w2, const float* __restrict__ b2) {
    int i = threadIdx.x;
    if (i < 288) {
        int d  = i / 144;
        int r  = i % 144;
        int wo = r / 16;
        int ic = r % 16;
        float s = 0.f;
        #pragma unroll 7
        for (int j = 0; j < 49; ++j)
            s += w2[(size_t)(d * 49 + j) * 144 + ic * 9 + wo];
        g_w2eff[i] = s * (1.0f / 49.0f);
    }
    if (i < 2) {
        float s = 0.f;
        #pragma unroll 7
        for (int j = 0; j < 49; ++j) s += b2[i * 49 + j];
        g_b2eff[i] = s * (1.0f / 49.0f);
    }
}

// ---------------------------------------------------------------------------
// Kernel 3: conv3x3 (2->16) + BN + ReLU. 1 px/thread (R2 shape), output
// packed fp16 pixel-major: 16 halfs = 2 x STG.128 per pixel.
// ---------------------------------------------------------------------------
__global__ void k_conv1(const float* __restrict__ w1,
                        const float* __restrict__ gamma, const float* __restrict__ beta,
                        const float* __restrict__ mean,  const float* __restrict__ var) {
    __shared__ float ws[288];
    __shared__ float sc[16], bi[16];
    int t = threadIdx.x;
    for (int i = t; i < 288; i += blockDim.x) ws[i] = w1[i];
    if (t < 16) {
        float s = gamma[t] * rsqrtf(var[t] + 1e-5f);
        sc[t] = s;
        bi[t] = beta[t] - mean[t] * s;
    }
    __syncthreads();

    int idx = blockIdx.x * blockDim.x + t;      // 0..262143
    int b   = idx >> 14;
    int rem = idx & 16383;
    int y = rem >> 7, x = rem & 127;

    const float* sfb = g_sf + (size_t)b * 2 * HWp;
    float v[18];
    #pragma unroll
    for (int ic = 0; ic < 2; ++ic)
        #pragma unroll
        for (int kh = 0; kh < 3; ++kh)
            #pragma unroll
            for (int kw = 0; kw < 3; ++kw) {
                int yy = y + kh - 1, xx = x + kw - 1;
                float val = 0.f;
                if (yy >= 0 && yy < HH && xx >= 0 && xx < WW)
                    val = sfb[ic * HWp + yy * WW + xx];
                v[ic * 9 + kh * 3 + kw] = val;
            }

    __align__(16) __half2 ho[8];
    #pragma unroll
    for (int p = 0; p < 8; ++p) {
        float a0 = 0.f, a1 = 0.f;
        #pragma unroll
        for (int k = 0; k < 18; ++k) {
            a0 = fmaf(v[k], ws[(2 * p)     * 18 + k], a0);
            a1 = fmaf(v[k], ws[(2 * p + 1) * 18 + k], a1);
        }
        a0 = fmaxf(fmaf(a0, sc[2 * p],     bi[2 * p]),     0.f);
        a1 = fmaxf(fmaf(a1, sc[2 * p + 1], bi[2 * p + 1]), 0.f);
        ho[p] = __floats2half2_rn(a0, a1);
    }

    uint4* dst = reinterpret_cast<uint4*>(g_h1h) + ((size_t)b * HWp + rem) * 2;
    const uint4* src = reinterpret_cast<const uint4*>(ho);
    dst[0] = src[0];
    dst[1] = src[1];
}

// ---------------------------------------------------------------------------
// Kernel 4: conv3x3 (16->2 eff) + bias, tanh*0.5, grid, bilinear sample.
// Pair-split: 2 threads/pixel, each loads its 8 fp16 channels per neighbor
// as one LDG.128, combines via one shfl_xor.
// ---------------------------------------------------------------------------
__global__ void k_off_sample() {
    __shared__ float4 ws4[72];     // transposed [d][wo][16] as float4s
    __shared__ float b2s[2];
    int t = threadIdx.x;
    if (t < 72) ws4[t] = reinterpret_cast<const float4*>(g_w2eff)[t];
    if (t < 2)  b2s[t] = g_b2eff[t];
    __syncthreads();

    int idx   = blockIdx.x * blockDim.x + t;   // 0..524287
    int q     = idx & 1;                       // half: channels 8q..8q+7
    int pixel = idx >> 1;                      // 0..262143
    int b     = pixel >> 14;
    int rem   = pixel & 16383;
    int y = rem >> 7, x = rem & 127;

    const uint4* hb = reinterpret_cast<const uint4*>(g_h1h) + (size_t)b * HWp * 2 + q;
    float ax = 0.f, ay = 0.f;

    #pragma unroll
    for (int dy = 0; dy < 3; ++dy) {
        int yy = y + dy - 1;
        if (yy < 0 || yy >= HH) continue;
        #pragma unroll
        for (int dx = 0; dx < 3; ++dx) {
            int xx = x + dx - 1;
            if (xx < 0 || xx >= WW) continue;
            uint4 hv = hb[(size_t)(yy * WW + xx) * 2];
            float2 c0 = __half22float2(*reinterpret_cast<__half2*>(&hv.x));
            float2 c1 = __half22float2(*reinterpret_cast<__half2*>(&hv.y));
            float2 c2 = __half22float2(*reinterpret_cast<__half2*>(&hv.z));
            float2 c3 = __half22float2(*reinterpret_cast<__half2*>(&hv.w));
            int wo = dy * 3 + dx;
            float4 wxa = ws4[wo * 4 + 2 * q], wxb = ws4[wo * 4 + 2 * q + 1];
            float4 wya = ws4[36 + wo * 4 + 2 * q], wyb = ws4[36 + wo * 4 + 2 * q + 1];
            ax = fmaf(c0.x, wxa.x, ax); ax = fmaf(c0.y, wxa.y, ax);
            ax = fmaf(c1.x, wxa.z, ax); ax = fmaf(c1.y, wxa.w, ax);
            ax = fmaf(c2.x, wxb.x, ax); ax = fmaf(c2.y, wxb.y, ax);
            ax = fmaf(c3.x, wxb.z, ax); ax = fmaf(c3.y, wxb.w, ax);
            ay = fmaf(c0.x, wya.x, ay); ay = fmaf(c0.y, wya.y, ay);
            ay = fmaf(c1.x, wya.z, ay); ay = fmaf(c1.y, wya.w, ay);
            ay = fmaf(c2.x, wyb.x, ay); ay = fmaf(c2.y, wyb.y, ay);
            ay = fmaf(c3.x, wyb.z, ay); ay = fmaf(c3.y, wyb.w, ay);
        }
    }

    ax += __shfl_xor_sync(0xffffffffu, ax, 1);
    ay += __shfl_xor_sync(0xffffffffu, ay, 1);

    if (q == 0) {
        ax += b2s[0];
        ay += b2s[1];
        float txo = tanhf(ax) * 0.5f;
        float tyo = tanhf(ay) * 0.5f;
        float gxv = fmaf((float)x, 2.0f / 127.0f, -1.0f) + txo;
        float gyv = fmaf((float)y, 2.0f / 127.0f, -1.0f) + tyo;
        gxv = fminf(fmaxf(gxv, -1.f), 1.f);
        gyv = fminf(fmaxf(gyv, -1.f), 1.f);

        float ixf = ((gxv + 1.0f) * (float)WW - 1.0f) * 0.5f;
        float iyf = ((gyv + 1.0f) * (float)HH - 1.0f) * 0.5f;
        float x0f = floorf(ixf), y0f = floorf(iyf);
        int x0 = (int)x0f, y0 = (int)y0f;
        int x1 = x0 + 1,   y1 = y0 + 1;
        float wx1 = ixf - x0f, wx0 = 1.0f - wx1;
        float wy1 = iyf - y0f, wy0 = 1.0f - wy1;

        const float* s0 = g_sf + (size_t)b * 2 * HWp;  // avg
        const float* s1 = s0 + HWp;                    // max

        float w00 = wx0 * wy0, w10 = wx1 * wy0, w01 = wx0 * wy1, w11 = wx1 * wy1;
        bool vx0 = (x0 >= 0) & (x0 < WW), vx1 = (x1 >= 0) & (x1 < WW);
        bool vy0 = (y0 >= 0) & (y0 < HH), vy1 = (y1 >= 0) & (y1 < HH);

        float o0 = 0.f, o1 = 0.f;
        if (vy0 & vx0) { int p = y0 * WW + x0; o0 = fmaf(s0[p], w00, o0); o1 = fmaf(s1[p], w00, o1); }
        if (vy0 & vx1) { int p = y0 * WW + x1; o0 = fmaf(s0[p], w10, o0); o1 = fmaf(s1[p], w10, o1); }
        if (vy1 & vx0) { int p = y1 * WW + x0; o0 = fmaf(s0[p], w01, o0); o1 = fmaf(s1[p], w01, o1); }
        if (vy1 & vx1) { int p = y1 * WW + x1; o0 = fmaf(s0[p], w11, o0); o1 = fmaf(s1[p], w11, o1); }

        g_samp[(size_t)b * 2 * HWp + rem]       = o0;
        g_samp[(size_t)b * 2 * HWp + HWp + rem] = o1;
    }
}

// ---------------------------------------------------------------------------
// Kernel 5: conv7x7 (2->1, pad 3) + sigmoid. 4 px/thread (aligned float4).
// ---------------------------------------------------------------------------
__global__ void k_attn(const float* __restrict__ aw, float* __restrict__ out) {
    __shared__ float ws[98];
    int t = threadIdx.x;
    if (t < 98) ws[t] = aw[t];
    __syncthreads();

    int idx = blockIdx.x * blockDim.x + t;      // 0..65535
    int b   = idx >> 12;
    int p4  = idx & 4095;
    int y   = p4 >> 5;
    int x4  = (p4 & 31) * 4;

    const float* sb = g_samp + (size_t)b * 2 * HWp;
    float acc[4] = {0.f, 0.f, 0.f, 0.f};

    #pragma unroll
    for (int ch = 0; ch < 2; ++ch)
        #pragma unroll
        for (int dy = 0; dy < 7; ++dy) {
            int yy = y + dy - 3;
            if (yy < 0 || yy >= HH) continue;
            const float* base = sb + ch * HWp + yy * WW + x4;
            float4 mv = *reinterpret_cast<const float4*>(base);
            float cl[10];
            if (x4 > 0) {
                float4 lv = *reinterpret_cast<const float4*>(base - 4);
                cl[0] = lv.y; cl[1] = lv.z; cl[2] = lv.w;
            } else {
                cl[0] = cl[1] = cl[2] = 0.f;
            }
            cl[3] = mv.x; cl[4] = mv.y; cl[5] = mv.z; cl[6] = mv.w;
            if (x4 < 124) {
                float4 rv = *reinterpret_cast<const float4*>(base + 4);
                cl[7] = rv.x; cl[8] = rv.y; cl[9] = rv.z;
            } else {
                cl[7] = cl[8] = cl[9] = 0.f;
            }
            #pragma unroll
            for (int kw = 0; kw < 7; ++kw) {
                float w = ws[ch * 49 + dy * 7 + kw];
                #pragma unroll
                for (int j = 0; j < 4; ++j)
                    acc[j] = fmaf(cl[kw + j], w, acc[j]);
            }
        }

    float4 o;
    o.x = 1.0f / (1.0f + expf(-acc[0]));
    o.y = 1.0f / (1.0f + expf(-acc[1]));
    o.z = 1.0f / (1.0f + expf(-acc[2]));
    o.w = 1.0f / (1.0f + expf(-acc[3]));
    *reinterpret_cast<float4*>(out + (size_t)b * HWp + y * WW + x4) = o;
}

// ---------------------------------------------------------------------------
extern "C" void kernel_launch(void* const* d_in, const int* in_sizes, int n_in,
                              void* d_out, int out_size) {
    const float* x     = (const float*)d_in[0];
    const float* w1    = (const float*)d_in[1];
    const float* gamma = (const float*)d_in[2];
    const float* beta  = (const float*)d_in[3];
    const float* mean  = (const float*)d_in[4];
    const float* var   = (const float*)d_in[5];
    const float* w2    = (const float*)d_in[6];
    const float* b2    = (const float*)d_in[7];
    const float* aw    = (const float*)d_in[8];
    float* out = (float*)d_out;

    k_reduce<<<128, 512>>>(x);
    k_w2eff<<<1, 512>>>(w2, b2);
    k_conv1<<<1024, 256>>>(w1, gamma, beta, mean, var);
    k_off_sample<<<2048, 256>>>();
    k_attn<<<256, 256>>>(aw, out);
}